// round 2
// baseline (speedup 1.0000x reference)
#include <cuda_runtime.h>
#include <math.h>
#include <stdint.h>
#include <stddef.h>

// Problem constants (shapes fixed by the dataset)
#define NN   10000
#define EE   160000
#define HD   32      // hidden
#define NDD  64      // node_dim
#define EDD  16      // edge_dim
#define MHH  128     // edge mlp hidden

// ---------------- scratch (device globals; no allocation allowed) ----------
__device__ int   g_is64;
__device__ int   g_src[EE], g_dst[EE];
__device__ int   g_cnt_src[NN], g_cnt_dst[NN];
__device__ int   g_off_src[NN + 1], g_off_dst[NN + 1];
__device__ int   g_cur_src[NN], g_cur_dst[NN];
__device__ int   g_ebysrc[EE], g_ebydst[EE];
__device__ float g_h[NN * HD];
__device__ float g_z[(size_t)EE * MHH];          // relu(ea@W1+b1)      82 MB
__device__ float g_W2t[HD * MHH * HD];           // [j][m*32+i] = W2[m][i*32+j]
__device__ float g_b2t[HD * HD];                 // [j][i] = b2[i*32+j]
__device__ float g_P[(size_t)NN * MHH * HD];     // [n][m*32+i]        164 MB
__device__ float g_C[NN * HD];
__device__ float g_msg[(size_t)EE * HD];         // per-edge message    20 MB
__device__ float g_agg[NN * HD];

// ---------------- setup kernels -------------------------------------------

// Detect int64 vs int32 edge_index: int64 little-endian => every odd 32-bit
// word of the first 128 (src) entries is 0 (values in [0,10000)).
__global__ void k_detect(const int* __restrict__ w) {
    __shared__ int ok;
    if (threadIdx.x == 0) ok = 1;
    __syncthreads();
    if (w[2 * threadIdx.x + 1] != 0) atomicExch(&ok, 0);
    __syncthreads();
    if (threadIdx.x == 0) g_is64 = ok;
}

__global__ void k_zero_counts(int nN) {
    int i = blockIdx.x * 256 + threadIdx.x;
    if (i < nN) { g_cnt_src[i] = 0; g_cnt_dst[i] = 0; }
}

// Extract src/dst as int32 (branch on detected dtype) + degree histograms.
__global__ void k_extract(const int* __restrict__ w, int nE) {
    int e = blockIdx.x * 256 + threadIdx.x;
    if (e >= nE) return;
    int is64 = g_is64;
    int s, d;
    if (is64) { s = w[2 * e]; d = w[2 * (nE + e)]; }
    else      { s = w[e];     d = w[nE + e]; }
    g_src[e] = s; g_dst[e] = d;
    atomicAdd(&g_cnt_src[s], 1);
    atomicAdd(&g_cnt_dst[d], 1);
}

// Single-block exclusive scan (blockIdx 0 -> src arrays, 1 -> dst arrays).
__global__ void k_scan(int nN) {
    int* cnt = blockIdx.x ? g_cnt_dst : g_cnt_src;
    int* off = blockIdx.x ? g_off_dst : g_off_src;
    int* cur = blockIdx.x ? g_cur_dst : g_cur_src;
    __shared__ int s[1024];
    __shared__ int sbase;
    int tid = threadIdx.x;
    if (tid == 0) sbase = 0;
    __syncthreads();
    for (int start = 0; start < nN; start += 1024) {
        int i = start + tid;
        int v = (i < nN) ? cnt[i] : 0;
        s[tid] = v;
        __syncthreads();
        for (int ofs = 1; ofs < 1024; ofs <<= 1) {
            int t = (tid >= ofs) ? s[tid - ofs] : 0;
            __syncthreads();
            s[tid] += t;
            __syncthreads();
        }
        int excl = sbase + s[tid] - v;
        if (i < nN) { off[i] = excl; cur[i] = excl; }
        __syncthreads();
        if (tid == 0) sbase += s[1023];
        __syncthreads();
    }
    if (tid == 0) off[nN] = sbase;
}

__global__ void k_fill(int nE) {
    int e = blockIdx.x * 256 + threadIdx.x;
    if (e >= nE) return;
    int s = g_src[e], d = g_dst[e];
    int p = atomicAdd(&g_cur_src[s], 1); g_ebysrc[p] = e;
    int q = atomicAdd(&g_cur_dst[d], 1); g_ebydst[q] = e;
}

// W2t[j*4096 + m*32 + i] = W2[m*1024 + i*32 + j]; b2t[j*32+i] = b2[i*32+j]
__global__ void k_w2t(const float* __restrict__ W2, const float* __restrict__ b2) {
    int t = blockIdx.x * 256 + threadIdx.x;
    if (t < HD * MHH * HD) {
        int j = t >> 12, m = (t >> 5) & 127, i = t & 31;
        g_W2t[t] = W2[m * 1024 + i * 32 + j];
    }
    int t2 = t - HD * MHH * HD;
    if (t2 >= 0 && t2 < HD * HD) {
        int j = t2 >> 5, i = t2 & 31;
        g_b2t[t2] = b2[i * 32 + j];
    }
}

// h0 = x @ Wp + bp   (warp per node)
__global__ __launch_bounds__(256) void k_h0(const float* __restrict__ x,
                                            const float* __restrict__ Wp,
                                            const float* __restrict__ bp, int nN) {
    __shared__ float Ws[NDD * HD];
    __shared__ float bs[HD];
    int tid = threadIdx.x;
    for (int i = tid; i < NDD * HD; i += 256) Ws[i] = Wp[i];
    if (tid < HD) bs[tid] = bp[tid];
    __syncthreads();
    int w = tid >> 5, lane = tid & 31;
    int n = blockIdx.x * 8 + w;
    if (n >= nN) return;
    float x0 = x[n * 64 + lane], x1 = x[n * 64 + 32 + lane];
    float acc = bs[lane];
#pragma unroll
    for (int j = 0; j < 32; j++) acc += __shfl_sync(0xffffffffu, x0, j) * Ws[j * 32 + lane];
#pragma unroll
    for (int j = 0; j < 32; j++) acc += __shfl_sync(0xffffffffu, x1, j) * Ws[(32 + j) * 32 + lane];
    g_h[n * 32 + lane] = acc;
}

// z = relu(ea @ W1 + b1)   (warp per edge)
__global__ __launch_bounds__(256) void k_z(const float* __restrict__ ea,
                                           const float* __restrict__ W1,
                                           const float* __restrict__ b1, int nE) {
    __shared__ float Ws[EDD * MHH];
    __shared__ float bs[MHH];
    int tid = threadIdx.x;
    for (int i = tid; i < EDD * MHH; i += 256) Ws[i] = W1[i];
    if (tid < MHH) bs[tid] = b1[tid];
    __syncthreads();
    int w = tid >> 5, lane = tid & 31;
    int e = blockIdx.x * 8 + w;
    if (e >= nE) return;
    float a0 = (lane < 16) ? ea[e * 16 + lane] : 0.f;
    float acc0 = bs[lane], acc1 = bs[32 + lane], acc2 = bs[64 + lane], acc3 = bs[96 + lane];
#pragma unroll
    for (int j = 0; j < 16; j++) {
        float a = __shfl_sync(0xffffffffu, a0, j);
        acc0 += a * Ws[j * 128 + lane];
        acc1 += a * Ws[j * 128 + 32 + lane];
        acc2 += a * Ws[j * 128 + 64 + lane];
        acc3 += a * Ws[j * 128 + 96 + lane];
    }
    float* zp = &g_z[(size_t)e * 128];
    zp[lane]      = fmaxf(acc0, 0.f);
    zp[32 + lane] = fmaxf(acc1, 0.f);
    zp[64 + lane] = fmaxf(acc2, 0.f);
    zp[96 + lane] = fmaxf(acc3, 0.f);
}

// ---------------- per-step kernels ----------------------------------------

// P[n, m*32+i] = sum_j h[n,j] * W2t[j, m*32+i]  : GEMM M=nN, N=4096, K=32
// 128x128 tile per block, 256 threads, 8x8 per thread.
__global__ __launch_bounds__(256) void k_P(int nN) {
    __shared__ float As[32 * 132];
    __shared__ float Bs[32 * 132];
    int tid = threadIdx.x;
    int bm = blockIdx.y * 128, bn = blockIdx.x * 128;
#pragma unroll
    for (int idx = tid; idx < 128 * 32; idx += 256) {
        int nl = idx >> 5, j = idx & 31;
        int n = bm + nl;
        As[j * 132 + nl] = (n < nN) ? g_h[n * 32 + j] : 0.f;
    }
#pragma unroll
    for (int idx = tid; idx < 32 * 128; idx += 256) {
        int k = idx >> 7, c = idx & 127;
        Bs[k * 132 + c] = g_W2t[k * 4096 + bn + c];
    }
    __syncthreads();
    int tx = tid & 15, ty = tid >> 4;
    float acc[8][8] = {};
#pragma unroll
    for (int k = 0; k < 32; k++) {
        float4 a0 = *(const float4*)&As[k * 132 + ty * 8];
        float4 a1 = *(const float4*)&As[k * 132 + ty * 8 + 4];
        float4 b0 = *(const float4*)&Bs[k * 132 + tx * 8];
        float4 b1 = *(const float4*)&Bs[k * 132 + tx * 8 + 4];
        float a[8] = {a0.x, a0.y, a0.z, a0.w, a1.x, a1.y, a1.z, a1.w};
        float b[8] = {b0.x, b0.y, b0.z, b0.w, b1.x, b1.y, b1.z, b1.w};
#pragma unroll
        for (int u = 0; u < 8; u++)
#pragma unroll
            for (int v = 0; v < 8; v++) acc[u][v] += a[u] * b[v];
    }
#pragma unroll
    for (int u = 0; u < 8; u++) {
        int n = bm + ty * 8 + u;
        if (n < nN) {
            float* dst = &g_P[(size_t)n * 4096 + bn + tx * 8];
            *(float4*)dst       = make_float4(acc[u][0], acc[u][1], acc[u][2], acc[u][3]);
            *(float4*)(dst + 4) = make_float4(acc[u][4], acc[u][5], acc[u][6], acc[u][7]);
        }
    }
}

// C[n,i] = sum_j h[n,j] * b2t[j*32+i]
__global__ __launch_bounds__(256) void k_C(int nN) {
    __shared__ float bs[HD * HD];
    int tid = threadIdx.x;
    for (int i = tid; i < HD * HD; i += 256) bs[i] = g_b2t[i];
    __syncthreads();
    int w = tid >> 5, lane = tid & 31;
    int n = blockIdx.x * 8 + w;
    if (n >= nN) return;
    float hv = g_h[n * 32 + lane];
    float acc = 0.f;
#pragma unroll
    for (int j = 0; j < 32; j++) acc += __shfl_sync(0xffffffffu, hv, j) * bs[j * 32 + lane];
    g_C[n * 32 + lane] = acc;
}

// msg[e,i] = C[src,i] + sum_m z[e,m]*P[src,m*32+i], edges grouped by src so
// each 16KB P row is read from DRAM once and reused in smem.
__global__ __launch_bounds__(128) void k_msg() {
    int n = blockIdx.x;
    int off = g_off_src[n];
    int d = g_off_src[n + 1] - off;
    if (d == 0) return;
    __shared__ float Pt[32 * 132];       // transposed: Pt[i*132 + m]
    __shared__ float zb[4][4][128];
    __shared__ float Cn[32];
    int tid = threadIdx.x, w = tid >> 5, lane = tid & 31;
    const float* Pg = &g_P[(size_t)n * 4096];
    for (int idx = tid; idx < 4096; idx += 128) {
        float v = Pg[idx];
        Pt[(idx & 31) * 132 + (idx >> 5)] = v;
    }
    if (tid < 32) Cn[tid] = g_C[n * 32 + tid];
    __syncthreads();

    for (int base = w * 4; base < d; base += 16) {
        int cnt = min(4, d - base);
        int eidx[4];
#pragma unroll
        for (int k = 0; k < 4; k++) {
            if (k < cnt) {
                int e = g_ebysrc[off + base + k];
                eidx[k] = e;
                const float* zp = &g_z[(size_t)e * 128];
#pragma unroll
                for (int q = 0; q < 4; q++) zb[w][k][q * 32 + lane] = zp[q * 32 + lane];
            }
        }
        __syncwarp();
        float acc[4];
#pragma unroll
        for (int k = 0; k < 4; k++) acc[k] = Cn[lane];
        const float4* prow = (const float4*)&Pt[lane * 132];
#pragma unroll 8
        for (int m4 = 0; m4 < 32; m4++) {
            float4 p = prow[m4];
#pragma unroll
            for (int k = 0; k < 4; k++) {
                float4 zv = *(const float4*)&zb[w][k][m4 * 4];
                acc[k] += p.x * zv.x + p.y * zv.y + p.z * zv.z + p.w * zv.w;
            }
        }
#pragma unroll
        for (int k = 0; k < 4; k++)
            if (k < cnt) g_msg[(size_t)eidx[k] * 32 + lane] = acc[k];
        __syncwarp();
    }
}

// agg[v] = sum of msg over incoming edges (dst-CSR gather, no atomics)
__global__ __launch_bounds__(256) void k_agg(int nN) {
    int tid = threadIdx.x, w = tid >> 5, lane = tid & 31;
    int n = blockIdx.x * 8 + w;
    if (n >= nN) return;
    int o = g_off_dst[n], d = g_off_dst[n + 1] - o;
    float acc = 0.f;
    for (int k = 0; k < d; k++) {
        int e = g_ebydst[o + k];
        acc += g_msg[(size_t)e * 32 + lane];
    }
    g_agg[n * 32 + lane] = acc;
}

// GRUCell (torch layout [r,z,n]) : warp per node
__global__ __launch_bounds__(256) void k_gru(const float* __restrict__ wih,
                                             const float* __restrict__ whh,
                                             const float* __restrict__ bih,
                                             const float* __restrict__ bhh,
                                             float* __restrict__ out, int nN) {
    __shared__ float wi[32 * 96];   // wi[j*96+k] = wih[k*32+j]
    __shared__ float wh[32 * 96];
    __shared__ float bi[96], bh[96];
    int tid = threadIdx.x;
    for (int idx = tid; idx < 3072; idx += 256) {
        int k = idx >> 5, j = idx & 31;
        wi[j * 96 + k] = wih[idx];
        wh[j * 96 + k] = whh[idx];
    }
    if (tid < 96) { bi[tid] = bih[tid]; bh[tid] = bhh[tid]; }
    __syncthreads();
    int w = tid >> 5, lane = tid & 31;
    int n = blockIdx.x * 8 + w;
    if (n >= nN) return;
    float av = g_agg[n * 32 + lane], hv = g_h[n * 32 + lane];
    float gi0 = bi[lane], gi1 = bi[32 + lane], gi2 = bi[64 + lane];
    float gh0 = bh[lane], gh1 = bh[32 + lane], gh2 = bh[64 + lane];
#pragma unroll
    for (int j = 0; j < 32; j++) {
        float a = __shfl_sync(0xffffffffu, av, j);
        float h = __shfl_sync(0xffffffffu, hv, j);
        gi0 += a * wi[j * 96 + lane];
        gi1 += a * wi[j * 96 + 32 + lane];
        gi2 += a * wi[j * 96 + 64 + lane];
        gh0 += h * wh[j * 96 + lane];
        gh1 += h * wh[j * 96 + 32 + lane];
        gh2 += h * wh[j * 96 + 64 + lane];
    }
    float r  = 1.f / (1.f + expf(-(gi0 + gh0)));
    float zz = 1.f / (1.f + expf(-(gi1 + gh1)));
    float nn = tanhf(gi2 + r * gh2);
    float hn = (1.f - zz) * nn + zz * hv;
    g_h[n * 32 + lane] = hn;
    out[n * 32 + lane] = hn;
}

// ---------------- launch ---------------------------------------------------

extern "C" void kernel_launch(void* const* d_in, const int* in_sizes, int n_in,
                              void* d_out, int out_size) {
    const float* x   = (const float*)d_in[0];
    const int*   ei  = (const int*)d_in[1];
    const float* ea  = (const float*)d_in[2];
    const float* Wp  = (const float*)d_in[3];
    const float* bp  = (const float*)d_in[4];
    const float* W1  = (const float*)d_in[5];
    const float* b1  = (const float*)d_in[6];
    const float* W2  = (const float*)d_in[7];
    const float* b2  = (const float*)d_in[8];
    const float* wih = (const float*)d_in[9];
    const float* whh = (const float*)d_in[10];
    const float* bih = (const float*)d_in[11];
    const float* bhh = (const float*)d_in[12];
    float* out = (float*)d_out;

    int nN = in_sizes[0] / NDD; if (nN > NN) nN = NN;
    int nE = in_sizes[2] / EDD; if (nE > EE) nE = EE;

    // ---- setup (per launch, deterministic) ----
    k_zero_counts<<<(nN + 255) / 256, 256>>>(nN);
    k_detect<<<1, 128>>>(ei);
    k_extract<<<(nE + 255) / 256, 256>>>(ei, nE);
    k_scan<<<2, 1024>>>(nN);
    k_fill<<<(nE + 255) / 256, 256>>>(nE);
    k_w2t<<<(HD * MHH * HD + HD * HD + 255) / 256, 256>>>(W2, b2);
    k_h0<<<(nN + 7) / 8, 256>>>(x, Wp, bp, nN);
    k_z<<<(nE + 7) / 8, 256>>>(ea, W1, b1, nE);

    // ---- 3 message-passing steps ----
    dim3 gP(32, (nN + 127) / 128);
    for (int step = 0; step < 3; step++) {
        k_P<<<gP, 256>>>(nN);
        k_C<<<(nN + 7) / 8, 256>>>(nN);
        k_msg<<<nN, 128>>>();
        k_agg<<<(nN + 7) / 8, 256>>>(nN);
        k_gru<<<(nN + 7) / 8, 256>>>(wih, whh, bih, bhh, out, nN);
    }
}